// round 1
// baseline (speedup 1.0000x reference)
#include <cuda_runtime.h>

// Problem constants (fixed by the dataset)
#define BB 131072
#define DD 128
#define KK 1024
#define BM 128
#define BN 64
#define XS_STRIDE 129   // transposed X tile row stride (floats) -> conflict-free frag reads
#define ES_STRIDE 65    // transposed E tile row stride (floats)

#define SMEM_FLOATS (DD*XS_STRIDE + DD*ES_STRIDE + BM + BN + BN + 8)
#define SMEM_BYTES  (SMEM_FLOATS * 4)

// Device scratch (no allocations allowed)
__device__ float g_loss;
__device__ float g_ee[KK];

// ---------------------------------------------------------------------------
// Kernel 0: per-codeword squared norms + zero the loss accumulator.
// One warp per codeword row (128 floats = 32 lanes x float4).
// ---------------------------------------------------------------------------
__global__ void vq_prep(const float* __restrict__ E) {
    int warp = threadIdx.x >> 5;
    int lane = threadIdx.x & 31;
    int k = blockIdx.x * 8 + warp;
    const float4* row = (const float4*)(E + (size_t)k * DD);
    float4 v = row[lane];
    float s = v.x * v.x + v.y * v.y + v.z * v.z + v.w * v.w;
    #pragma unroll
    for (int o = 16; o > 0; o >>= 1) s += __shfl_xor_sync(0xffffffffu, s, o);
    if (lane == 0) g_ee[k] = s;
    if (blockIdx.x == 0 && threadIdx.x == 0) g_loss = 0.0f;
}

// ---------------------------------------------------------------------------
// Main kernel: one CTA handles 128 input rows vs the whole codebook.
//   - X tile [128 x 128] transposed in smem
//   - loop over 16 codebook tiles of 64, transposed in smem
//   - 8x4 register tile per thread (thread grid 16x16; row = ty+16i, k = tx+16j)
//   - epilogue: scaled distance, running argmin in registers
//   - final: 16-lane butterfly argmin reduce, gather codeword -> out,
//            commitment-loss partial -> atomic accumulator
// ---------------------------------------------------------------------------
__global__ __launch_bounds__(256, 2) void vq_main(
    const float* __restrict__ X, const float* __restrict__ E,
    const float* __restrict__ S, float* __restrict__ out, int out_size)
{
    extern __shared__ float sm[];
    float* xs   = sm;                       // [DD][XS_STRIDE] transposed X tile
    float* es   = xs + DD * XS_STRIDE;      // [DD][ES_STRIDE] transposed E tile
    float* xx   = es + DD * ES_STRIDE;      // [BM] row squared norms
    float* ee_s = xx + BM;                  // [BN]
    float* s_s  = ee_s + BN;                // [BN]
    float* red  = s_s + BN;                 // [8] loss warp partials

    const int tid = threadIdx.x;
    const int tx  = tid & 15;
    const int ty  = tid >> 4;
    const int b0  = blockIdx.x * BM;

    // ---- load X tile (transposed store; coalesced float4 global reads) ----
    {
        const float4* Xg = (const float4*)(X + (size_t)b0 * DD);
        #pragma unroll
        for (int it = 0; it < (BM * 32) / 256; ++it) {
            int idx = tid + it * 256;
            int row = idx >> 5;
            int d4  = idx & 31;
            float4 v = Xg[row * 32 + d4];
            xs[(4 * d4 + 0) * XS_STRIDE + row] = v.x;
            xs[(4 * d4 + 1) * XS_STRIDE + row] = v.y;
            xs[(4 * d4 + 2) * XS_STRIDE + row] = v.z;
            xs[(4 * d4 + 3) * XS_STRIDE + row] = v.w;
        }
    }
    __syncthreads();

    // ---- per-row squared norms (use es space as scratch before first tile) ----
    {
        float* xpart = es;  // 256 floats scratch
        int row = tid & 127, half = tid >> 7;
        float ssum = 0.0f;
        const float* p = xs + (half * 64) * XS_STRIDE + row;
        #pragma unroll 8
        for (int d = 0; d < 64; ++d) { float v = *p; ssum += v * v; p += XS_STRIDE; }
        xpart[tid] = ssum;
        __syncthreads();
        if (tid < BM) xx[tid] = xpart[tid] + xpart[tid + 128];
        __syncthreads();
    }

    float xr[8];
    #pragma unroll
    for (int i = 0; i < 8; ++i) xr[i] = xx[ty + 16 * i];

    float minv[8];
    int   mini[8];
    #pragma unroll
    for (int i = 0; i < 8; ++i) { minv[i] = 3.4e38f; mini[i] = 0; }

    // ---- loop over codebook tiles ----
    for (int kt = 0; kt < KK / BN; ++kt) {
        const int k0 = kt * BN;
        __syncthreads();  // protect es reuse across iterations
        {
            const float4* Eg = (const float4*)(E + (size_t)k0 * DD);
            #pragma unroll
            for (int it = 0; it < (BN * 32) / 256; ++it) {
                int idx = tid + it * 256;
                int kk  = idx >> 5;
                int d4  = idx & 31;
                float4 v = Eg[kk * 32 + d4];
                es[(4 * d4 + 0) * ES_STRIDE + kk] = v.x;
                es[(4 * d4 + 1) * ES_STRIDE + kk] = v.y;
                es[(4 * d4 + 2) * ES_STRIDE + kk] = v.z;
                es[(4 * d4 + 3) * ES_STRIDE + kk] = v.w;
            }
        }
        if (tid < BN) { ee_s[tid] = g_ee[k0 + tid]; s_s[tid] = S[k0 + tid]; }
        __syncthreads();

        float acc[8][4];
        #pragma unroll
        for (int i = 0; i < 8; ++i)
            #pragma unroll
            for (int j = 0; j < 4; ++j) acc[i][j] = 0.0f;

        const float* xp = xs + ty;
        const float* ep = es + tx;
        #pragma unroll 4
        for (int d = 0; d < DD; ++d) {
            float xf[8], ef[4];
            #pragma unroll
            for (int i = 0; i < 8; ++i) xf[i] = xp[16 * i];
            #pragma unroll
            for (int j = 0; j < 4; ++j) ef[j] = ep[16 * j];
            #pragma unroll
            for (int i = 0; i < 8; ++i)
                #pragma unroll
                for (int j = 0; j < 4; ++j)
                    acc[i][j] = fmaf(xf[i], ef[j], acc[i][j]);
            xp += XS_STRIDE;
            ep += ES_STRIDE;
        }

        // epilogue: scaled distances + running argmin (k ascending -> first-min ties)
        #pragma unroll
        for (int j = 0; j < 4; ++j) {
            int   kk = tx + 16 * j;
            float s  = s_s[kk];
            float e2 = ee_s[kk];
            int   kg = k0 + kk;
            #pragma unroll
            for (int i = 0; i < 8; ++i) {
                float v = s * (xr[i] + e2 - 2.0f * acc[i][j]);
                if (v < minv[i]) { minv[i] = v; mini[i] = kg; }
            }
        }
    }

    // ---- cross-thread argmin reduce within the 16-lane row groups ----
    #pragma unroll
    for (int o = 1; o <= 8; o <<= 1) {
        #pragma unroll
        for (int i = 0; i < 8; ++i) {
            float ov = __shfl_xor_sync(0xffffffffu, minv[i], o);
            int   oi = __shfl_xor_sync(0xffffffffu, mini[i], o);
            if (ov < minv[i] || (ov == minv[i] && oi < mini[i])) {
                minv[i] = ov; mini[i] = oi;
            }
        }
    }

    // ---- outputs: indices, quantized gather, loss partial ----
    const bool full = (out_size >= BB * DD + 1 + BB);
    float lsum = 0.0f;
    #pragma unroll
    for (int i = 0; i < 8; ++i) {
        int row = ty + 16 * i;
        int b   = b0 + row;
        int idx = mini[i];
        if (tx == 0 && full) out[(size_t)BB * DD + 1 + b] = (float)idx;

        const float4* q4 = (const float4*)(E + (size_t)idx * DD);
        float4 a = q4[tx * 2 + 0];
        float4 c = q4[tx * 2 + 1];

        int d0 = tx * 8;
        float x0 = xs[(d0 + 0) * XS_STRIDE + row];
        float x1 = xs[(d0 + 1) * XS_STRIDE + row];
        float x2 = xs[(d0 + 2) * XS_STRIDE + row];
        float x3 = xs[(d0 + 3) * XS_STRIDE + row];
        float x4 = xs[(d0 + 4) * XS_STRIDE + row];
        float x5 = xs[(d0 + 5) * XS_STRIDE + row];
        float x6 = xs[(d0 + 6) * XS_STRIDE + row];
        float x7 = xs[(d0 + 7) * XS_STRIDE + row];

        float d0v = a.x - x0, d1v = a.y - x1, d2v = a.z - x2, d3v = a.w - x3;
        float d4v = c.x - x4, d5v = c.y - x5, d6v = c.z - x6, d7v = c.w - x7;
        lsum += d0v * d0v + d1v * d1v + d2v * d2v + d3v * d3v
              + d4v * d4v + d5v * d5v + d6v * d6v + d7v * d7v;

        float4* o4 = (float4*)(out + (size_t)b * DD);
        o4[tx * 2 + 0] = a;
        o4[tx * 2 + 1] = c;
    }

    // loss block reduce -> global atomic
    #pragma unroll
    for (int o = 16; o > 0; o >>= 1) lsum += __shfl_xor_sync(0xffffffffu, lsum, o);
    if ((tid & 31) == 0) red[tid >> 5] = lsum;
    __syncthreads();
    if (tid == 0) {
        float t = 0.0f;
        #pragma unroll
        for (int w = 0; w < 8; ++w) t += red[w];
        atomicAdd(&g_loss, t);
    }
}

// ---------------------------------------------------------------------------
// Kernel 2: finalize loss scalar
// ---------------------------------------------------------------------------
__global__ void vq_fin(float* __restrict__ out, int out_size) {
    if (out_size >= BB * DD + 1)
        out[BB * DD] = 0.25f * g_loss / (float)((size_t)BB * DD);
}

extern "C" void kernel_launch(void* const* d_in, const int* in_sizes, int n_in,
                              void* d_out, int out_size) {
    const float* X = (const float*)d_in[0];   // inputs [B, D]
    const float* E = (const float*)d_in[1];   // embedding [K, D]
    const float* S = (const float*)d_in[2];   // ema_cluster_size [K]
    float* out = (float*)d_out;

    cudaFuncSetAttribute(vq_main, cudaFuncAttributeMaxDynamicSharedMemorySize, SMEM_BYTES);

    vq_prep<<<KK / 8, 256>>>(E);
    vq_main<<<BB / BM, 256, SMEM_BYTES>>>(X, E, S, out, out_size);
    vq_fin<<<1, 1>>>(out, out_size);
}

// round 3
// speedup vs baseline: 1.7392x; 1.7392x over previous
#include <cuda_runtime.h>
#include <cstdint>

// ---------------------------------------------------------------------------
// VQ-VAE EMA quantizer via 3xTF32 mma.sync (sm_103-compatible, no tcgen05).
//   v[b,k] = s_k*(||x_b||^2 + ||e_k||^2 - 2<x_b,e_k>) = p_k + q_k*(dot + h_b)
//   dot = x_hi*e_hi + x_hi*e_lo + x_lo*e_hi  (TF32 splits, fp32 accumulate)
// ---------------------------------------------------------------------------

#define BB 131072
#define DD 128
#define KK 1024
#define BM 128
#define BN 32
#define NITER (KK/BN)   // 32

// smem byte offsets
#define SM_AH   0         // 64KB x_hi frag-permuted
#define SM_AL   65536     // 64KB x_lo
#define SM_B    131072    // 2 stages x 32KB (hi 16KB | lo 16KB)
#define SM_P    196608    // 4KB p_k
#define SM_Q    200704    // 4KB q_k
#define SM_XX   204800    // 512B h_r = -0.5*||x_r||^2
#define SM_MIN  205312    // 512B float
#define SM_MINI 205824    // 512B int
#define SM_RED  206336    // 32B
#define SMEM_BYTES 206848

__device__ float g_loss;
__device__ float g_p[KK];
__device__ float g_q[KK];
__device__ float g_ebh[KK * DD];   // frag-permuted tf32 codebook hi (per 32-tile)
__device__ float g_ebl[KK * DD];   // lo

__device__ __forceinline__ float tf32r(float x) {
    uint32_t u;
    asm("cvt.rna.tf32.f32 %0, %1;" : "=r"(u) : "f"(x));
    return __uint_as_float(u);
}
__device__ __forceinline__ void mma_t(float c[4], const uint4& a, uint32_t b0, uint32_t b1) {
    asm volatile(
        "mma.sync.aligned.m16n8k8.row.col.f32.tf32.tf32.f32 "
        "{%0,%1,%2,%3},{%4,%5,%6,%7},{%8,%9},{%0,%1,%2,%3};"
        : "+f"(c[0]), "+f"(c[1]), "+f"(c[2]), "+f"(c[3])
        : "r"(a.x), "r"(a.y), "r"(a.z), "r"(a.w), "r"(b0), "r"(b1));
}
__device__ __forceinline__ void cp16(uint32_t dst_smem, const void* src) {
    asm volatile("cp.async.cg.shared.global [%0], [%1], 16;"
                 :: "r"(dst_smem), "l"(src) : "memory");
}
__device__ __forceinline__ uint32_t smem_u32(const void* p) {
    uint32_t a;
    asm("{ .reg .u64 t; cvta.to.shared.u64 t, %1; cvt.u32.u64 %0, t; }"
        : "=r"(a) : "l"(p));
    return a;
}

// ---------------------------------------------------------------------------
// prep: split codebook into tf32 hi/lo in B-frag-permuted tile layout;
// p = s*||e||^2, q = -2s; zero loss.
// ---------------------------------------------------------------------------
__global__ void vq_prep(const float* __restrict__ E, const float* __restrict__ S) {
    int wid = threadIdx.x >> 5, lane = threadIdx.x & 31;
    int k = blockIdx.x * 8 + wid;
    float4 v = ((const float4*)(E + (size_t)k * DD))[lane];
    float s2 = v.x * v.x + v.y * v.y + v.z * v.z + v.w * v.w;
    #pragma unroll
    for (int o = 16; o > 0; o >>= 1) s2 += __shfl_xor_sync(0xffffffffu, s2, o);

    float hi[4], lo[4];
    hi[0] = tf32r(v.x); lo[0] = tf32r(v.x - hi[0]);
    hi[1] = tf32r(v.y); lo[1] = tf32r(v.y - hi[1]);
    hi[2] = tf32r(v.z); lo[2] = tf32r(v.z - hi[2]);
    hi[3] = tf32r(v.w); lo[3] = tf32r(v.w - hi[3]);

    // layout within 32-codeword tile: elem (kk in chunk kc, n local):
    // np=n/16, nb=n%16, sub=nb/8, nn=nb%8; lane_s=nn*4+(kk&3); reg=(kk>>2)+2*sub
    // word offset = ((kc*2+np)*32 + lane_s)*4 + reg;  tile = 4096 words
    int t = k >> 5, n = k & 31;
    int np = n >> 4, nb = n & 15, sub = nb >> 3, nn = nb & 7;
    int d0 = lane * 4;
    int kc = d0 >> 3;
    int regbase = ((d0 & 7) >> 2) + 2 * sub;
    size_t tb = (size_t)t * 4096;
    #pragma unroll
    for (int j = 0; j < 4; ++j) {
        int ls = nn * 4 + j;
        size_t w = tb + (size_t)((kc * 2 + np) * 32 + ls) * 4 + regbase;
        g_ebh[w] = hi[j];
        g_ebl[w] = lo[j];
    }
    if (lane == 0) {
        float s = S[k];
        g_p[k] = s * s2;
        g_q[k] = -2.0f * s;
    }
    if (blockIdx.x == 0 && threadIdx.x == 0) g_loss = 0.0f;
}

// ---------------------------------------------------------------------------
// main
// ---------------------------------------------------------------------------
__global__ __launch_bounds__(256, 1) void vq_main(
    const float* __restrict__ X, const float* __restrict__ E,
    float* __restrict__ out, int out_size)
{
    extern __shared__ char smem[];
    const uint32_t sb = smem_u32(smem);
    const int tid    = threadIdx.x;
    const int lane   = tid & 31;
    const int wid    = tid >> 5;
    const int warp_m = wid >> 1;
    const int warp_n = wid & 1;
    const int b0     = blockIdx.x * BM;

    float* AHw = (float*)(smem + SM_AH);
    float* ALw = (float*)(smem + SM_AL);
    float* xx  = (float*)(smem + SM_XX);
    float* ps  = (float*)(smem + SM_P);
    float* qs  = (float*)(smem + SM_Q);

    // ---- X load + tf32 split into A-frag layout + h_r ----
    {
        const float4* Xg = (const float4*)(X + (size_t)b0 * DD);
        #pragma unroll
        for (int it = 0; it < 16; ++it) {
            int idx = tid + it * 256;
            int r = idx >> 5;        // uniform per warp
            int d4 = idx & 31;
            float4 v = Xg[r * 32 + d4];
            float n = v.x * v.x + v.y * v.y + v.z * v.z + v.w * v.w;
            #pragma unroll
            for (int o = 16; o > 0; o >>= 1) n += __shfl_xor_sync(0xffffffffu, n, o);
            if (lane == 0) xx[r] = -0.5f * n;
            float e[4] = {v.x, v.y, v.z, v.w};
            int mt = r >> 4, rm = r & 15;
            int kc = d4 >> 1;
            int reg = (rm >> 3) + ((d4 & 1) << 1);
            int base = ((kc * 8 + mt) * 32) * 4 + reg;
            #pragma unroll
            for (int j = 0; j < 4; ++j) {
                float h = tf32r(e[j]);
                float l = tf32r(e[j] - h);
                int w = base + ((rm & 7) * 4 + j) * 4;
                AHw[w] = h;
                ALw[w] = l;
            }
        }
    }
    // ---- p/q -> smem ----
    #pragma unroll
    for (int j = 0; j < 4; ++j) { int i = tid + 256 * j; ps[i] = g_p[i]; qs[i] = g_q[i]; }

    // ---- preload B tile 0 -> stage 0 ----
    {
        uint32_t dh = sb + SM_B + tid * 16;
        const char* shc = (const char*)g_ebh + tid * 16;
        const char* slc = (const char*)g_ebl + tid * 16;
        #pragma unroll
        for (int r = 0; r < 4; ++r) {
            cp16(dh + r * 4096,          shc + r * 4096);
            cp16(dh + 16384 + r * 4096,  slc + r * 4096);
        }
        asm volatile("cp.async.commit_group;" ::: "memory");
    }
    asm volatile("cp.async.wait_group 0;" ::: "memory");
    __syncthreads();

    // h values for this thread's 4 rows
    float hh[2][2];
    #pragma unroll
    for (int mt = 0; mt < 2; ++mt)
        #pragma unroll
        for (int pr = 0; pr < 2; ++pr)
            hh[mt][pr] = xx[warp_m * 32 + mt * 16 + (lane >> 2) + 8 * pr];

    float minv[4] = {3.4e38f, 3.4e38f, 3.4e38f, 3.4e38f};
    int   mini[4] = {0, 0, 0, 0};

    const uint4* Ah = (const uint4*)(smem + SM_AH) + warp_m * 64 + lane;
    const uint4* Al = (const uint4*)(smem + SM_AL) + warp_m * 64 + lane;

    for (int t = 0; t < NITER; ++t) {
        const int stage = t & 1;
        // prefetch tile t+1 into other stage
        if (t + 1 < NITER) {
            uint32_t dh = sb + SM_B + (stage ^ 1) * 32768 + tid * 16;
            const char* shc = (const char*)g_ebh + (size_t)(t + 1) * 16384 + tid * 16;
            const char* slc = (const char*)g_ebl + (size_t)(t + 1) * 16384 + tid * 16;
            #pragma unroll
            for (int r = 0; r < 4; ++r) {
                cp16(dh + r * 4096,         shc + r * 4096);
                cp16(dh + 16384 + r * 4096, slc + r * 4096);
            }
            asm volatile("cp.async.commit_group;" ::: "memory");
        }

        const uint4* Bh = (const uint4*)(smem + SM_B + stage * 32768) + warp_n * 32 + lane;
        const uint4* Bl = Bh + 1024;

        float acc[2][2][4];
        #pragma unroll
        for (int mt = 0; mt < 2; ++mt)
            #pragma unroll
            for (int nt = 0; nt < 2; ++nt)
                #pragma unroll
                for (int j = 0; j < 4; ++j) acc[mt][nt][j] = 0.0f;

        #pragma unroll
        for (int kc = 0; kc < 16; ++kc) {
            uint4 ah0 = Ah[kc * 256];
            uint4 ah1 = Ah[kc * 256 + 32];
            uint4 al0 = Al[kc * 256];
            uint4 al1 = Al[kc * 256 + 32];
            uint4 bh  = Bh[kc * 64];
            uint4 bl  = Bl[kc * 64];
            mma_t(acc[0][0], ah0, bh.x, bh.y);
            mma_t(acc[0][0], ah0, bl.x, bl.y);
            mma_t(acc[0][0], al0, bh.x, bh.y);
            mma_t(acc[0][1], ah0, bh.z, bh.w);
            mma_t(acc[0][1], ah0, bl.z, bl.w);
            mma_t(acc[0][1], al0, bh.z, bh.w);
            mma_t(acc[1][0], ah1, bh.x, bh.y);
            mma_t(acc[1][0], ah1, bl.x, bl.y);
            mma_t(acc[1][0], al1, bh.x, bh.y);
            mma_t(acc[1][1], ah1, bh.z, bh.w);
            mma_t(acc[1][1], ah1, bl.z, bl.w);
            mma_t(acc[1][1], al1, bh.z, bh.w);
        }

        // epilogue: scaled distance + running argmin
        #pragma unroll
        for (int nt = 0; nt < 2; ++nt) {
            int k0 = t * 32 + warp_n * 16 + nt * 8 + ((lane & 3) << 1);
            float p0 = ps[k0], p1 = ps[k0 + 1];
            float q0 = qs[k0], q1 = qs[k0 + 1];
            #pragma unroll
            for (int mt = 0; mt < 2; ++mt) {
                float v00 = fmaf(q0, acc[mt][nt][0] + hh[mt][0], p0);
                float v01 = fmaf(q1, acc[mt][nt][1] + hh[mt][0], p1);
                float v10 = fmaf(q0, acc[mt][nt][2] + hh[mt][1], p0);
                float v11 = fmaf(q1, acc[mt][nt][3] + hh[mt][1], p1);
                int r0 = mt * 2, r1 = mt * 2 + 1;
                if (v00 < minv[r0]) { minv[r0] = v00; mini[r0] = k0; }
                if (v01 < minv[r0]) { minv[r0] = v01; mini[r0] = k0 + 1; }
                if (v10 < minv[r1]) { minv[r1] = v10; mini[r1] = k0; }
                if (v11 < minv[r1]) { minv[r1] = v11; mini[r1] = k0 + 1; }
            }
        }

        asm volatile("cp.async.wait_group 0;" ::: "memory");
        __syncthreads();
    }

    // ---- cross-lane argmin reduce (lanes differing in bits 0..1 share rows) ----
    #pragma unroll
    for (int o = 1; o <= 2; o <<= 1) {
        #pragma unroll
        for (int i = 0; i < 4; ++i) {
            float ov = __shfl_xor_sync(0xffffffffu, minv[i], o);
            int   oi = __shfl_xor_sync(0xffffffffu, mini[i], o);
            if (ov < minv[i] || (ov == minv[i] && oi < mini[i])) {
                minv[i] = ov; mini[i] = oi;
            }
        }
    }

    float* min_s  = (float*)(smem + SM_MIN);
    int*   mini_s = (int*)(smem + SM_MINI);
    if (warp_n == 0 && (lane & 3) == 0) {
        #pragma unroll
        for (int mt = 0; mt < 2; ++mt)
            #pragma unroll
            for (int pr = 0; pr < 2; ++pr) {
                int r = warp_m * 32 + mt * 16 + (lane >> 2) + 8 * pr;
                min_s[r] = minv[mt * 2 + pr];
                mini_s[r] = mini[mt * 2 + pr];
            }
    }
    __syncthreads();
    if (warp_n == 1 && (lane & 3) == 0) {
        #pragma unroll
        for (int mt = 0; mt < 2; ++mt)
            #pragma unroll
            for (int pr = 0; pr < 2; ++pr) {
                int r = warp_m * 32 + mt * 16 + (lane >> 2) + 8 * pr;
                float v1 = minv[mt * 2 + pr];
                int   i1 = mini[mt * 2 + pr];
                float v0 = min_s[r];
                int   i0 = mini_s[r];
                if (v1 < v0 || (v1 == v0 && i1 < i0)) { min_s[r] = v1; mini_s[r] = i1; }
            }
    }
    __syncthreads();

    // ---- outputs ----
    const bool full = (out_size >= BB * DD + 1 + BB);
    if (tid < BM && full)
        out[(size_t)BB * DD + 1 + b0 + tid] = (float)mini_s[tid];

    // gather codeword rows -> z_embed
    {
        int r = tid >> 1, hf = tid & 1;
        int idx = mini_s[r];
        const float4* Eq = (const float4*)(E + (size_t)idx * DD) + hf * 16;
        float4* Oq = (float4*)(out + (size_t)(b0 + r) * DD) + hf * 16;
        #pragma unroll
        for (int j = 0; j < 16; ++j) Oq[j] = Eq[j];
    }

    // commitment loss: d_row = minv / s_idx = -2*minv/q_idx
    float lsum = 0.0f;
    if (tid < BM) {
        int idx = mini_s[tid];
        lsum = -2.0f * min_s[tid] / qs[idx];
    }
    #pragma unroll
    for (int o = 16; o > 0; o >>= 1) lsum += __shfl_xor_sync(0xffffffffu, lsum, o);
    float* red = (float*)(smem + SM_RED);
    if (wid < 4 && lane == 0) red[wid] = lsum;
    __syncthreads();
    if (tid == 0) atomicAdd(&g_loss, red[0] + red[1] + red[2] + red[3]);
}

__global__ void vq_fin(float* __restrict__ out, int out_size) {
    if (out_size >= BB * DD + 1)
        out[BB * DD] = 0.25f * g_loss / (float)((size_t)BB * DD);
}

extern "C" void kernel_launch(void* const* d_in, const int* in_sizes, int n_in,
                              void* d_out, int out_size) {
    const float* X = (const float*)d_in[0];
    const float* E = (const float*)d_in[1];
    const float* S = (const float*)d_in[2];
    float* out = (float*)d_out;

    cudaFuncSetAttribute(vq_main, cudaFuncAttributeMaxDynamicSharedMemorySize, SMEM_BYTES);

    vq_prep<<<KK / 8, 256>>>(E, S);
    vq_main<<<BB / BM, 256, SMEM_BYTES>>>(X, E, out, out_size);
    vq_fin<<<1, 1>>>(out, out_size);
}